// round 15
// baseline (speedup 1.0000x reference)
#include <cuda_runtime.h>
#include <cuda_fp16.h>
#include <cstdint>

#define BB 32
#define NN 512
#define DINN 768
#define DOUTT 256
#define NEGV -9.0e15f
#define SLOPE 0.2f

// ---------------------------------------------------------------------------
// Scratch (allocation-free). Referenced ONLY in device code.
// ---------------------------------------------------------------------------
__device__ __half g_WT[DOUTT * DINN];                   // W^T fp16 [dout][din]
__device__ __half g_WhT[(long)BB * DOUTT * NN];         // Wh^T fp16 [b][dout][node]
__device__ float g_s1[BB * NN];
__device__ float g_s2[BB * NN];

// ---------------------------------------------------------------------------
__device__ __forceinline__ uint32_t smem_u32(const void* p) {
    uint32_t a;
    asm("{ .reg .u64 t; cvta.to.shared.u64 t, %1; cvt.u32.u64 %0, t; }" : "=r"(a) : "l"(p));
    return a;
}
__device__ __forceinline__ uint32_t pk2h(float a, float b) {
    __half2 hh = __floats2half2_rn(a, b);
    return *(uint32_t*)&hh;
}
__device__ __forceinline__ void cpa16(uint32_t s, const void* g) {
    asm volatile("cp.async.cg.shared.global [%0], [%1], 16;" :: "r"(s), "l"(g));
}

#define LDSM_X4(R, A)                                                         \
    asm volatile("ldmatrix.sync.aligned.m8n8.x4.shared.b16 {%0,%1,%2,%3}, [%4];" \
        : "=r"((R)[0]), "=r"((R)[1]), "=r"((R)[2]), "=r"((R)[3]) : "r"(A))

#define MMA16816(D, A, B0, B1)                                                \
    asm volatile("mma.sync.aligned.m16n8k16.row.col.f32.f16.f16.f32 "         \
        "{%0,%1,%2,%3},{%4,%5,%6,%7},{%8,%9},{%0,%1,%2,%3};"                  \
        : "+f"((D)[0]), "+f"((D)[1]), "+f"((D)[2]), "+f"((D)[3])              \
        : "r"((A)[0]), "r"((A)[1]), "r"((A)[2]), "r"((A)[3]), "r"(B0), "r"(B1))

// G1: A(128x32 fp16, stride 80) | B(256x32 fp16, stride 80); 3 stages
#define G1_A    0
#define G1_BH   10240
#define G1_BUF  30720
#define G1_RING (3 * G1_BUF)           // 92160
#define STG1    132                    // epi: st[dout*132 + node], 256x128 fp32
#define G1_PS1  135168
#define G1_PS2  (G1_PS1 + 1024)
#define G1_POS  (G1_PS2 + 1024)
#define G1_SMEM (G1_POS + 512)         // 137728

// G2 fused: A = att tile 128x512 fp16, row stride 1040 (conflict-free)
#define F_SA    0
#define F_SAROW 1040
#define F_SB    133120
#define F_SBUF  20480
#define F_SS2   (F_SB + 2 * F_SBUF)    // 174080: s2[512] fp32
#define F_SS1   (F_SS2 + 2048)         // s1[128] fp32
#define G2_SMEM (F_SS1 + 512)          // 176640
#define STG2    264                    // epi: st[node*264 + dout], 128x256 fp32

// ---------------------------------------------------------------------------
// Pre-pass: W [din][dout] fp32 -> W^T fp16 [dout][din]
// ---------------------------------------------------------------------------
__global__ __launch_bounds__(256)
void k_transW(const float* __restrict__ W)
{
    __shared__ float t[32][33];
    const int k0 = blockIdx.x * 32, n0 = blockIdx.y * 32;
    const int tx = threadIdx.x & 31, ty = threadIdx.x >> 5;
    #pragma unroll
    for (int j = 0; j < 4; j++) {
        int r = ty + j * 8;
        t[r][tx] = W[(long)(k0 + r) * DOUTT + n0 + tx];
    }
    __syncthreads();
    #pragma unroll
    for (int j = 0; j < 4; j++) {
        int r = ty + j * 8;
        g_WT[(long)(n0 + r) * DINN + k0 + tx] = __float2half_rn(t[tx][r]);
    }
}

// ---------------------------------------------------------------------------
// GEMM1: D[128 x 256] = h[128xK] * W^T, K=768, single fp16 product.
// 8 warps of 64x64 (2M x 4N) -> MMA:LDSM = 4.0. 3-stage B ring; A reg-staged.
// grid (NN/128=4, BB) = 128 CTAs. Epilogue: WhT fp16 + fused s1/s2.
// ---------------------------------------------------------------------------
__global__ __launch_bounds__(256, 1)
void g1_gemm(const float* __restrict__ hsrc,
             const int* __restrict__ pos, const float* __restrict__ pt,
             const float* __restrict__ a1v, const float* __restrict__ a2v)
{
    extern __shared__ char smem[];
    const uint32_t sbase = smem_u32(smem);
    const int tid = threadIdx.x, lane = tid & 31, wid = tid >> 5;
    const int wm = wid & 1, wn = wid >> 1;
    const int b = blockIdx.y;
    const int rowBase = blockIdx.x * 128;

    float acc[4][8][4];
    #pragma unroll
    for (int i = 0; i < 4; i++)
        #pragma unroll
        for (int j = 0; j < 8; j++)
            #pragma unroll
            for (int r = 0; r < 4; r++) acc[i][j][r] = 0.f;

    // A register staging: 4 float4/thread/stage (128 rows x 32 k fp32)
    const float* Abase = hsrc + ((long)b * NN + rowBase) * DINN;
    float4 fa[4];

    auto ALOADR = [&](int kc) {
        #pragma unroll
        for (int i = 0; i < 4; i++) {
            int idx = i * 256 + tid;
            int r = idx >> 3, c4 = idx & 7;
            fa[i] = *(const float4*)(Abase + (long)r * DINN + kc + c4 * 4);
        }
    };
    auto ASTORE = [&](int s) {
        char* bufc = smem + s * G1_BUF;
        #pragma unroll
        for (int i = 0; i < 4; i++) {
            int idx = i * 256 + tid;
            int r = idx >> 3, c4 = idx & 7;
            *(uint2*)(bufc + G1_A + r * 80 + c4 * 8) =
                make_uint2(pk2h(fa[i].x, fa[i].y), pk2h(fa[i].z, fa[i].w));
        }
    };
    auto ISSUE_B = [&](int kc, int s) {
        const uint32_t sb2 = sbase + s * G1_BUF;
        #pragma unroll
        for (int i = 0; i < 4; i++) {   // B: 256 rows x 64 B
            int idx = i * 256 + tid;
            int r = idx >> 2, c4 = idx & 3;
            cpa16(sb2 + G1_BH + r * 80 + c4 * 16,
                  g_WT + (long)r * DINN + kc + c4 * 8);
        }
        asm volatile("cp.async.commit_group;" ::: "memory");
    };

    const int arow = (wm * 64 + ((lane >> 3) & 1) * 8 + (lane & 7)) * 80;
    const int brow = (wn * 64 + ((lane >> 3) & 1) * 8 + (lane & 7)) * 80;

    auto COMPUTE = [&](int s) {
        const uint32_t base = sbase + s * G1_BUF;
        #pragma unroll
        for (int k16 = 0; k16 < 2; k16++) {
            const int kb = (k16 * 16 + (lane >> 4) * 8) * 2;
            uint32_t af[4][4];
            #pragma unroll
            for (int am = 0; am < 4; am++)
                LDSM_X4(af[am], base + G1_A + arow + am * 16 * 80 + kb);
            #pragma unroll
            for (int pr = 0; pr < 4; pr++) {
                uint32_t bh[4];
                LDSM_X4(bh, base + G1_BH + brow + pr * 16 * 80 + kb);
                #pragma unroll
                for (int od = 0; od < 2; od++) {
                    const int an = pr * 2 + od;
                    #pragma unroll
                    for (int am = 0; am < 4; am++)
                        MMA16816(acc[am][an], af[am], bh[od], bh[od + 2]);
                }
            }
        }
    };

    const int nT = DINN / 32;     // 24
    ALOADR(0);  ISSUE_B(0, 0);  ASTORE(0);
    ALOADR(32); ISSUE_B(32, 1); ASTORE(1);
    #pragma unroll 1
    for (int t = 0; t < nT; ++t) {
        if (t + 2 < nT) ALOADR((t + 2) * 32);
        if (t + 2 < nT) asm volatile("cp.async.wait_group 1;" ::: "memory");
        else            asm volatile("cp.async.wait_group 0;" ::: "memory");
        __syncthreads();
        if (t + 2 < nT) {
            ISSUE_B((t + 2) * 32, (t + 2) % 3);
            ASTORE((t + 2) % 3);
        }
        COMPUTE(t % 3);
    }
    __syncthreads();

    // ---- epilogue ----
    float* st  = (float*)smem;                 // [256 dout][132] fp32
    float* ps1 = (float*)(smem + G1_PS1);      // [2][128]
    float* ps2 = (float*)(smem + G1_PS2);
    int* pos_s = (int*)(smem + G1_POS);        // 128 ints

    #pragma unroll
    for (int am = 0; am < 4; am++)
        #pragma unroll
        for (int an = 0; an < 8; an++) {
            const int r0 = wm * 64 + am * 16 + (lane >> 2);           // node
            const int c0 = wn * 64 + an * 8 + (lane & 3) * 2;         // dout
            st[c0 * STG1 + r0]           = acc[am][an][0];
            st[(c0 + 1) * STG1 + r0]     = acc[am][an][1];
            st[c0 * STG1 + r0 + 8]       = acc[am][an][2];
            st[(c0 + 1) * STG1 + r0 + 8] = acc[am][an][3];
        }
    if (tid < 128) pos_s[tid] = pos[b * NN + rowBase + tid];
    __syncthreads();

    // pass A: add pos-emb, write WhT fp16 (coalesced over node), update stage
    #pragma unroll 2
    for (int i = 0; i < 128; i++) {
        int idx = i * 256 + tid;
        int dl = idx >> 7, nl = idx & 127;
        float v = st[dl * STG1 + nl] + __ldg(pt + (long)pos_s[nl] * DOUTT + dl);
        st[dl * STG1 + nl] = v;
        g_WhT[((long)b * DOUTT + dl) * NN + rowBase + nl] = __float2half_rn(v);
    }
    __syncthreads();

    // pass B: fused s1/s2 (2 partials per node)
    {
        const int node = tid & 127, q = tid >> 7;
        float v1 = 0.f, v2 = 0.f;
        #pragma unroll 4
        for (int c = 0; c < 128; c++) {
            int dl = q * 128 + c;
            float v = st[dl * STG1 + node];
            v1 += v * __ldg(a1v + dl);
            v2 += v * __ldg(a2v + dl);
        }
        ps1[q * 128 + node] = v1;
        ps2[q * 128 + node] = v2;
    }
    __syncthreads();
    if (tid < 128) {
        g_s1[b * NN + rowBase + tid] = ps1[tid] + ps1[128 + tid];
        g_s2[b * NN + rowBase + tid] = ps2[tid] + ps2[128 + tid];
    }
}

// ---------------------------------------------------------------------------
// GEMM2 fused: softmax prologue (att rows 128x512 -> d_out fp32 + smem fp16),
// then hp[128x256] = att * WhT. 8 warps of 64x64; B-only 2-stage ring.
// grid (4, BB) = 128 CTAs.
// ---------------------------------------------------------------------------
__global__ __launch_bounds__(256, 1)
void g2_fused(const int* __restrict__ adj, float* __restrict__ att,
              float* __restrict__ hp)
{
    extern __shared__ char smem[];
    const uint32_t sbase = smem_u32(smem);
    const int tid = threadIdx.x, lane = tid & 31, wid = tid >> 5;
    const int wm = wid & 1, wn = wid >> 1;
    const int b = blockIdx.y;
    const int rowBase = blockIdx.x * 128;

    auto ISSUE_B = [&](int kc, int s) {
        const uint32_t sb2 = sbase + F_SB + s * F_SBUF;
        #pragma unroll
        for (int i = 0; i < 4; i++) {   // B: WhT 256 rows x 64 B
            int idx = i * 256 + tid;
            int r = idx >> 2, c4 = idx & 3;
            long go = ((long)b * DOUTT + r) * NN + kc + c4 * 8;
            cpa16(sb2 + r * 80 + c4 * 16, g_WhT + go);
        }
        asm volatile("cp.async.commit_group;" ::: "memory");
    };

    ISSUE_B(0, 0);   // overlap first B stage with softmax

    // ---- softmax prologue: 8 warps x 16 rows ----
    float* s2s = (float*)(smem + F_SS2);
    float* s1s = (float*)(smem + F_SS1);
    if (tid < 128) ((float4*)s2s)[tid] = ((const float4*)(g_s2 + b * NN))[tid];
    if (tid < 128) s1s[tid] = g_s1[b * NN + rowBase + tid];
    __syncthreads();

    #pragma unroll 1
    for (int rr = 0; rr < 16; rr++) {
        const int r = wid * 16 + rr;
        const long abase = ((long)b * NN + rowBase + r) * NN;
        const float s1v = s1s[r];
        float ev[4][4];
        float mx = -3.4e38f;
        #pragma unroll
        for (int c = 0; c < 4; c++) {
            const int j0 = c * 128 + lane * 4;
            int4 a4 = *(const int4*)(adj + abase + j0);
            float4 s2v = *(const float4*)(s2s + j0);
            float x;
            x = s1v + s2v.x; x = x > 0.f ? x : SLOPE * x; ev[c][0] = (a4.x > 0) ? x : NEGV;
            x = s1v + s2v.y; x = x > 0.f ? x : SLOPE * x; ev[c][1] = (a4.y > 0) ? x : NEGV;
            x = s1v + s2v.z; x = x > 0.f ? x : SLOPE * x; ev[c][2] = (a4.z > 0) ? x : NEGV;
            x = s1v + s2v.w; x = x > 0.f ? x : SLOPE * x; ev[c][3] = (a4.w > 0) ? x : NEGV;
            mx = fmaxf(mx, fmaxf(fmaxf(ev[c][0], ev[c][1]), fmaxf(ev[c][2], ev[c][3])));
        }
        #pragma unroll
        for (int o = 16; o; o >>= 1) mx = fmaxf(mx, __shfl_xor_sync(0xffffffffu, mx, o));
        float sum = 0.f;
        #pragma unroll
        for (int c = 0; c < 4; c++)
            #pragma unroll
            for (int u = 0; u < 4; u++) {
                ev[c][u] = __expf(ev[c][u] - mx);
                sum += ev[c][u];
            }
        #pragma unroll
        for (int o = 16; o; o >>= 1) sum += __shfl_xor_sync(0xffffffffu, sum, o);
        const float inv = 1.f / sum;
        #pragma unroll
        for (int c = 0; c < 4; c++) {
            const int j0 = c * 128 + lane * 4;
            float v0 = ev[c][0] * inv, v1 = ev[c][1] * inv;
            float v2 = ev[c][2] * inv, v3 = ev[c][3] * inv;
            *(float4*)(att + abase + j0) = make_float4(v0, v1, v2, v3);
            *(uint2*)(smem + F_SA + r * F_SAROW + j0 * 2) =
                make_uint2(pk2h(v0, v1), pk2h(v2, v3));
        }
    }
    __syncthreads();   // A tile complete

    // ---- mainloop ----
    float acc[4][8][4];
    #pragma unroll
    for (int i = 0; i < 4; i++)
        #pragma unroll
        for (int j = 0; j < 8; j++)
            #pragma unroll
            for (int r = 0; r < 4; r++) acc[i][j][r] = 0.f;

    const int arow = (wm * 64 + ((lane >> 3) & 1) * 8 + (lane & 7)) * F_SAROW;
    const int brow = (wn * 64 + ((lane >> 3) & 1) * 8 + (lane & 7)) * 80;

    auto COMPUTE = [&](int t, int s) {
        const uint32_t abase2 = sbase + F_SA + arow + t * 64;
        const uint32_t bbase  = sbase + F_SB + s * F_SBUF;
        #pragma unroll
        for (int k16 = 0; k16 < 2; k16++) {
            const int kb = (k16 * 16 + (lane >> 4) * 8) * 2;
            uint32_t af[4][4];
            #pragma unroll
            for (int am = 0; am < 4; am++)
                LDSM_X4(af[am], abase2 + am * 16 * F_SAROW + kb);
            #pragma unroll
            for (int pr = 0; pr < 4; pr++) {
                uint32_t bh[4];
                LDSM_X4(bh, bbase + brow + pr * 16 * 80 + kb);
                #pragma unroll
                for (int od = 0; od < 2; od++) {
                    const int an = pr * 2 + od;
                    #pragma unroll
                    for (int am = 0; am < 4; am++)
                        MMA16816(acc[am][an], af[am], bh[od], bh[od + 2]);
                }
            }
        }
    };

    const int nT = NN / 32;       // 16
    #pragma unroll 1
    for (int t = 0; t < nT; ++t) {
        asm volatile("cp.async.wait_group 0;" ::: "memory");
        __syncthreads();
        if (t + 1 < nT) ISSUE_B((t + 1) * 32, (t + 1) & 1);
        COMPUTE(t, t & 1);
    }
    __syncthreads();

    // ---- epilogue: stage row-major, coalesced float4 out ----
    float* st = (float*)smem;                  // [128 node][264] fp32
    #pragma unroll
    for (int am = 0; am < 4; am++)
        #pragma unroll
        for (int an = 0; an < 8; an++) {
            const int r0 = wm * 64 + am * 16 + (lane >> 2);
            const int c0 = wn * 64 + an * 8 + (lane & 3) * 2;
            st[r0 * STG2 + c0]           = acc[am][an][0];
            st[r0 * STG2 + c0 + 1]       = acc[am][an][1];
            st[(r0 + 8) * STG2 + c0]     = acc[am][an][2];
            st[(r0 + 8) * STG2 + c0 + 1] = acc[am][an][3];
        }
    __syncthreads();
    #pragma unroll 4
    for (int i = 0; i < 32; i++) {
        int fid = i * 256 + tid;
        int r = fid >> 6, c4 = fid & 63;
        float4 v = *(const float4*)&st[r * STG2 + c4 * 4];
        *(float4*)&hp[((long)b * NN + rowBase + r) * DOUTT + c4 * 4] = v;
    }
}

// ---------------------------------------------------------------------------
extern "C" void kernel_launch(void* const* d_in, const int* in_sizes, int n_in,
                              void* d_out, int out_size)
{
    const float* h   = (const float*)d_in[0];
    const int*   adj = (const int*)  d_in[1];
    const int*   pos = (const int*)  d_in[2];
    const float* W   = (const float*)d_in[3];
    const float* a1  = (const float*)d_in[4];
    const float* a2  = (const float*)d_in[5];
    const float* pt  = (const float*)d_in[6];

    float* out = (float*)d_out;
    float* hp  = out;                              // [B,N,DOUT]
    float* att = out + (long)BB * NN * DOUTT;      // [B,N,N]

    static int smem_set = 0;
    if (!smem_set) {
        cudaFuncSetAttribute(g1_gemm, cudaFuncAttributeMaxDynamicSharedMemorySize, G1_SMEM);
        cudaFuncSetAttribute(g2_fused, cudaFuncAttributeMaxDynamicSharedMemorySize, G2_SMEM);
        smem_set = 1;
    }

    dim3 gT(DINN / 32, DOUTT / 32);                // (24, 8)
    k_transW<<<gT, 256>>>(W);

    dim3 gG(NN / 128, BB);                         // (4, 32) = 128 CTAs
    g1_gemm<<<gG, 256, G1_SMEM>>>(h, pos, pt, a1, a2);

    g2_fused<<<gG, 256, G2_SMEM>>>(adj, att, hp);
}

// round 16
// speedup vs baseline: 1.1390x; 1.1390x over previous
#include <cuda_runtime.h>
#include <cuda_fp16.h>
#include <cstdint>

#define BB 32
#define NN 512
#define DINN 768
#define DOUTT 256
#define NEGV -9.0e15f
#define SLOPE 0.2f

// ---------------------------------------------------------------------------
// Scratch (allocation-free). Referenced ONLY in device code.
// ---------------------------------------------------------------------------
__device__ __half g_WT[DOUTT * DINN];                   // W^T fp16 [dout][din]
__device__ __half g_WhT[(long)BB * DOUTT * NN];         // Wh^T fp16 [b][dout][node]
__device__ float g_s1[BB * NN];
__device__ float g_s2[BB * NN];

// ---------------------------------------------------------------------------
__device__ __forceinline__ uint32_t smem_u32(const void* p) {
    uint32_t a;
    asm("{ .reg .u64 t; cvta.to.shared.u64 t, %1; cvt.u32.u64 %0, t; }" : "=r"(a) : "l"(p));
    return a;
}
__device__ __forceinline__ uint32_t pk2h(float a, float b) {
    __half2 hh = __floats2half2_rn(a, b);
    return *(uint32_t*)&hh;
}
__device__ __forceinline__ void cpa16(uint32_t s, const void* g) {
    asm volatile("cp.async.cg.shared.global [%0], [%1], 16;" :: "r"(s), "l"(g));
}

#define LDSM_X4(R, A)                                                         \
    asm volatile("ldmatrix.sync.aligned.m8n8.x4.shared.b16 {%0,%1,%2,%3}, [%4];" \
        : "=r"((R)[0]), "=r"((R)[1]), "=r"((R)[2]), "=r"((R)[3]) : "r"(A))

#define MMA16816(D, A, B0, B1)                                                \
    asm volatile("mma.sync.aligned.m16n8k16.row.col.f32.f16.f16.f32 "         \
        "{%0,%1,%2,%3},{%4,%5,%6,%7},{%8,%9},{%0,%1,%2,%3};"                  \
        : "+f"((D)[0]), "+f"((D)[1]), "+f"((D)[2]), "+f"((D)[3])              \
        : "r"((A)[0]), "r"((A)[1]), "r"((A)[2]), "r"((A)[3]), "r"(B0), "r"(B1))

// G1: A(64x32 fp16) | B(256x32 fp16), rows stride 80 B; 4 stages
#define G1_A   0
#define G1_BH  5120
#define G1_BUF 25600
#define G1_NS  4
#define G1_RING (G1_NS * G1_BUF)       // 102400
#define G1_SMEM (G1_RING + 256)        // 102656 -> 2 CTAs/SM
#define STG1 68                        // epi: st[dout*68 + node], 256x64

// G2 fused: A = full att tile 64x512 fp16, row stride 1040 B (conflict-free)
//           B ring: 2 stages x (256 rows x 32 k, stride 80 B)
#define F_SA    0
#define F_SAROW 1040
#define F_SB    66560
#define F_SBUF  20480
#define F_SS2   (F_SB + 2 * F_SBUF)    // 107520: s2[512] fp32
#define F_SS1   (F_SS2 + 2048)         // s1[64] fp32
#define G2_SMEM (F_SS1 + 256)          // 109824 -> 2 CTAs/SM
#define STG2 264                       // epi stage: st[node*264 + dout], 64x256

// ---------------------------------------------------------------------------
// Pre-pass: W [din][dout] fp32 -> W^T fp16 [dout][din]
// ---------------------------------------------------------------------------
__global__ __launch_bounds__(256)
void k_transW(const float* __restrict__ W)
{
    __shared__ float t[32][33];
    const int k0 = blockIdx.x * 32, n0 = blockIdx.y * 32;
    const int tx = threadIdx.x & 31, ty = threadIdx.x >> 5;
    #pragma unroll
    for (int j = 0; j < 4; j++) {
        int r = ty + j * 8;
        t[r][tx] = W[(long)(k0 + r) * DOUTT + n0 + tx];
    }
    __syncthreads();
    #pragma unroll
    for (int j = 0; j < 4; j++) {
        int r = ty + j * 8;
        g_WT[(long)(n0 + r) * DINN + k0 + tx] = __float2half_rn(t[tx][r]);
    }
}

// ---------------------------------------------------------------------------
// GEMM1: D[64 x 256] = h[64xK] * W^T, K=768, single fp16 product.
// 4-stage ring; A LDG issued at iter top, dependent STS AFTER compute so the
// global latency is hidden by the MMA phase. grid (8, BB) = 256 CTAs.
// Epilogue: WhT fp16 + fused s1/s2.
// ---------------------------------------------------------------------------
__global__ __launch_bounds__(256, 2)
void g1_gemm(const float* __restrict__ hsrc,
             const int* __restrict__ pos, const float* __restrict__ pt,
             const float* __restrict__ a1v, const float* __restrict__ a2v)
{
    extern __shared__ char smem[];
    const uint32_t sbase = smem_u32(smem);
    const int tid = threadIdx.x, lane = tid & 31, wid = tid >> 5;
    const int b = blockIdx.y;
    const int rowBase = blockIdx.x * 64;

    float acc[4][4][4];
    #pragma unroll
    for (int i = 0; i < 4; i++)
        #pragma unroll
        for (int j = 0; j < 4; j++)
            #pragma unroll
            for (int r = 0; r < 4; r++) acc[i][j][r] = 0.f;

    const float* Abase = hsrc + ((long)b * NN + rowBase) * DINN;
    float4 fa[2];

    auto ALOADR = [&](int kc) {
        #pragma unroll
        for (int i = 0; i < 2; i++) {
            int idx = i * 256 + tid;
            int r = idx >> 3, c4 = idx & 7;
            fa[i] = *(const float4*)(Abase + (long)r * DINN + kc + c4 * 4);
        }
    };
    auto ASTORE = [&](int s) {
        char* bufc = smem + s * G1_BUF;
        #pragma unroll
        for (int i = 0; i < 2; i++) {
            int idx = i * 256 + tid;
            int r = idx >> 3, c4 = idx & 7;
            *(uint2*)(bufc + G1_A + r * 80 + c4 * 8) =
                make_uint2(pk2h(fa[i].x, fa[i].y), pk2h(fa[i].z, fa[i].w));
        }
    };
    auto ISSUE_B = [&](int kc, int s) {
        const uint32_t sb2 = sbase + s * G1_BUF;
        #pragma unroll
        for (int i = 0; i < 4; i++) {   // B: 256 rows x 64 B
            int idx = i * 256 + tid;
            int r = idx >> 2, c4 = idx & 3;
            cpa16(sb2 + G1_BH + r * 80 + c4 * 16,
                  g_WT + (long)r * DINN + kc + c4 * 8);
        }
        asm volatile("cp.async.commit_group;" ::: "memory");
    };

    const int arow = (((lane >> 3) & 1) * 8 + (lane & 7)) * 80;
    const int brow = (wid * 32 + ((lane >> 3) & 1) * 8 + (lane & 7)) * 80;

    auto COMPUTE = [&](int s) {
        const uint32_t base = sbase + s * G1_BUF;
        #pragma unroll
        for (int k16 = 0; k16 < 2; k16++) {
            const int kb = (k16 * 16 + (lane >> 4) * 8) * 2;
            uint32_t af[4][4];
            #pragma unroll
            for (int am = 0; am < 4; am++)
                LDSM_X4(af[am], base + G1_A + arow + am * 16 * 80 + kb);
            #pragma unroll
            for (int pr = 0; pr < 2; pr++) {
                uint32_t bh[4];
                LDSM_X4(bh, base + G1_BH + brow + pr * 16 * 80 + kb);
                #pragma unroll
                for (int od = 0; od < 2; od++) {
                    const int an = pr * 2 + od;
                    #pragma unroll
                    for (int am = 0; am < 4; am++)
                        MMA16816(acc[am][an], af[am], bh[od], bh[od + 2]);
                }
            }
        }
    };

    // 4-stage ring; ASTORE(t+3) deferred to after COMPUTE(t) so the A LDGs
    // issued at iter top have the whole MMA phase to complete.
    const int nT = DINN / 32;     // 24
    ALOADR(0);  ISSUE_B(0, 0);  ASTORE(0);
    ALOADR(32); ISSUE_B(32, 1); ASTORE(1);
    ALOADR(64); ISSUE_B(64, 2); ASTORE(2);
    #pragma unroll 1
    for (int t = 0; t < nT; ++t) {
        const bool pf = (t + 3 < nT);
        if (pf) ALOADR((t + 3) * 32);
        if (pf) asm volatile("cp.async.wait_group 2;" ::: "memory");
        else    asm volatile("cp.async.wait_group 0;" ::: "memory");
        __syncthreads();
        if (pf) ISSUE_B((t + 3) * 32, (t + 3) % G1_NS);
        COMPUTE(t % G1_NS);
        if (pf) ASTORE((t + 3) % G1_NS);
    }
    __syncthreads();

    // ---- epilogue ----
    float* st  = (float*)smem;                 // [256 dout][68] fp32
    float* ps1 = (float*)(smem + 69632);       // [4][64]
    float* ps2 = (float*)(smem + 70656);
    int* pos_s = (int*)(smem + G1_RING);       // 64 ints

    #pragma unroll
    for (int am = 0; am < 4; am++)
        #pragma unroll
        for (int an = 0; an < 4; an++) {
            const int r0 = am * 16 + (lane >> 2);
            const int c0 = wid * 32 + an * 8 + (lane & 3) * 2;
            st[c0 * STG1 + r0]           = acc[am][an][0];
            st[(c0 + 1) * STG1 + r0]     = acc[am][an][1];
            st[c0 * STG1 + r0 + 8]       = acc[am][an][2];
            st[(c0 + 1) * STG1 + r0 + 8] = acc[am][an][3];
        }
    if (tid < 64) pos_s[tid] = pos[b * NN + rowBase + tid];
    __syncthreads();

    // pass A: add pos-emb, write WhT fp16, update stage
    #pragma unroll 2
    for (int i = 0; i < 64; i++) {
        int idx = i * 256 + tid;
        int dl = idx >> 6, nl = idx & 63;
        float v = st[dl * STG1 + nl] + __ldg(pt + (long)pos_s[nl] * DOUTT + dl);
        st[dl * STG1 + nl] = v;
        g_WhT[((long)b * DOUTT + dl) * NN + rowBase + nl] = __float2half_rn(v);
    }
    __syncthreads();

    // pass B: fused s1/s2
    {
        const int node = tid & 63, q = tid >> 6;
        float v1 = 0.f, v2 = 0.f;
        #pragma unroll 4
        for (int c = 0; c < 64; c++) {
            int dl = q * 64 + c;
            float v = st[dl * STG1 + node];
            v1 += v * __ldg(a1v + dl);
            v2 += v * __ldg(a2v + dl);
        }
        ps1[q * 64 + node] = v1;
        ps2[q * 64 + node] = v2;
    }
    __syncthreads();
    if (tid < 64) {
        float s1 = ps1[tid] + ps1[64 + tid] + ps1[128 + tid] + ps1[192 + tid];
        float s2 = ps2[tid] + ps2[64 + tid] + ps2[128 + tid] + ps2[192 + tid];
        g_s1[b * NN + rowBase + tid] = s1;
        g_s2[b * NN + rowBase + tid] = s2;
    }
}

// ---------------------------------------------------------------------------
// GEMM2 fused: softmax prologue (att rows 64x512 -> d_out fp32 + smem fp16),
// then hp[64x256] = att * WhT. B-only 2-stage ring. grid (8, BB).
// (unchanged from R14 best)
// ---------------------------------------------------------------------------
__global__ __launch_bounds__(256, 2)
void g2_fused(const int* __restrict__ adj, float* __restrict__ att,
              float* __restrict__ hp)
{
    extern __shared__ char smem[];
    const uint32_t sbase = smem_u32(smem);
    const int tid = threadIdx.x, lane = tid & 31, wid = tid >> 5;
    const int b = blockIdx.y;
    const int rowBase = blockIdx.x * 64;

    auto ISSUE_B = [&](int kc, int s) {
        const uint32_t sb2 = sbase + F_SB + s * F_SBUF;
        #pragma unroll
        for (int i = 0; i < 4; i++) {   // B: WhT 256 rows x 64 B
            int idx = i * 256 + tid;
            int r = idx >> 2, c4 = idx & 3;
            long go = ((long)b * DOUTT + r) * NN + kc + c4 * 8;
            cpa16(sb2 + r * 80 + c4 * 16, g_WhT + go);
        }
        asm volatile("cp.async.commit_group;" ::: "memory");
    };

    ISSUE_B(0, 0);   // overlap first B stage with softmax

    // ---- softmax prologue: 8 warps x 8 rows ----
    float* s2s = (float*)(smem + F_SS2);
    float* s1s = (float*)(smem + F_SS1);
    if (tid < 128) ((float4*)s2s)[tid] = ((const float4*)(g_s2 + b * NN))[tid];
    if (tid < 64)  s1s[tid] = g_s1[b * NN + rowBase + tid];
    __syncthreads();

    #pragma unroll 1
    for (int rr = 0; rr < 8; rr++) {
        const int r = wid * 8 + rr;
        const long abase = ((long)b * NN + rowBase + r) * NN;
        const float s1v = s1s[r];
        float ev[4][4];
        float mx = -3.4e38f;
        #pragma unroll
        for (int c = 0; c < 4; c++) {
            const int j0 = c * 128 + lane * 4;
            int4 a4 = *(const int4*)(adj + abase + j0);
            float4 s2v = *(const float4*)(s2s + j0);
            float x;
            x = s1v + s2v.x; x = x > 0.f ? x : SLOPE * x; ev[c][0] = (a4.x > 0) ? x : NEGV;
            x = s1v + s2v.y; x = x > 0.f ? x : SLOPE * x; ev[c][1] = (a4.y > 0) ? x : NEGV;
            x = s1v + s2v.z; x = x > 0.f ? x : SLOPE * x; ev[c][2] = (a4.z > 0) ? x : NEGV;
            x = s1v + s2v.w; x = x > 0.f ? x : SLOPE * x; ev[c][3] = (a4.w > 0) ? x : NEGV;
            mx = fmaxf(mx, fmaxf(fmaxf(ev[c][0], ev[c][1]), fmaxf(ev[c][2], ev[c][3])));
        }
        #pragma unroll
        for (int o = 16; o; o >>= 1) mx = fmaxf(mx, __shfl_xor_sync(0xffffffffu, mx, o));
        float sum = 0.f;
        #pragma unroll
        for (int c = 0; c < 4; c++)
            #pragma unroll
            for (int u = 0; u < 4; u++) {
                ev[c][u] = __expf(ev[c][u] - mx);
                sum += ev[c][u];
            }
        #pragma unroll
        for (int o = 16; o; o >>= 1) sum += __shfl_xor_sync(0xffffffffu, sum, o);
        const float inv = 1.f / sum;
        #pragma unroll
        for (int c = 0; c < 4; c++) {
            const int j0 = c * 128 + lane * 4;
            float v0 = ev[c][0] * inv, v1 = ev[c][1] * inv;
            float v2 = ev[c][2] * inv, v3 = ev[c][3] * inv;
            *(float4*)(att + abase + j0) = make_float4(v0, v1, v2, v3);
            *(uint2*)(smem + F_SA + r * F_SAROW + j0 * 2) =
                make_uint2(pk2h(v0, v1), pk2h(v2, v3));
        }
    }
    __syncthreads();   // A tile complete

    // ---- mainloop: A from resident smem, B 2-stage ring ----
    float acc[4][4][4];
    #pragma unroll
    for (int i = 0; i < 4; i++)
        #pragma unroll
        for (int j = 0; j < 4; j++)
            #pragma unroll
            for (int r = 0; r < 4; r++) acc[i][j][r] = 0.f;

    const int arow = (((lane >> 3) & 1) * 8 + (lane & 7)) * F_SAROW;
    const int brow = (wid * 32 + ((lane >> 3) & 1) * 8 + (lane & 7)) * 80;

    auto COMPUTE = [&](int t, int s) {
        const uint32_t abase2 = sbase + F_SA + arow + t * 64;
        const uint32_t bbase  = sbase + F_SB + s * F_SBUF;
        #pragma unroll
        for (int k16 = 0; k16 < 2; k16++) {
            const int kb = (k16 * 16 + (lane >> 4) * 8) * 2;
            uint32_t af[4][4];
            #pragma unroll
            for (int am = 0; am < 4; am++)
                LDSM_X4(af[am], abase2 + am * 16 * F_SAROW + kb);
            #pragma unroll
            for (int pr = 0; pr < 2; pr++) {
                uint32_t bh[4];
                LDSM_X4(bh, bbase + brow + pr * 16 * 80 + kb);
                #pragma unroll
                for (int od = 0; od < 2; od++) {
                    const int an = pr * 2 + od;
                    #pragma unroll
                    for (int am = 0; am < 4; am++)
                        MMA16816(acc[am][an], af[am], bh[od], bh[od + 2]);
                }
            }
        }
    };

    const int nT = NN / 32;       // 16
    #pragma unroll 1
    for (int t = 0; t < nT; ++t) {
        asm volatile("cp.async.wait_group 0;" ::: "memory");
        __syncthreads();
        if (t + 1 < nT) ISSUE_B((t + 1) * 32, (t + 1) & 1);
        COMPUTE(t, t & 1);
    }
    __syncthreads();

    // ---- epilogue: stage row-major, coalesced float4 out ----
    float* st = (float*)smem;
    #pragma unroll
    for (int am = 0; am < 4; am++)
        #pragma unroll
        for (int an = 0; an < 4; an++) {
            const int r0 = am * 16 + (lane >> 2);
            const int c0 = wid * 32 + an * 8 + (lane & 3) * 2;
            st[r0 * STG2 + c0]           = acc[am][an][0];
            st[r0 * STG2 + c0 + 1]       = acc[am][an][1];
            st[(r0 + 8) * STG2 + c0]     = acc[am][an][2];
            st[(r0 + 8) * STG2 + c0 + 1] = acc[am][an][3];
        }
    __syncthreads();
    #pragma unroll 4
    for (int i = 0; i < 16; i++) {
        int fid = i * 256 + tid;
        int r = fid >> 6, c4 = fid & 63;
        float4 v = *(const float4*)&st[r * STG2 + c4 * 4];
        *(float4*)&hp[((long)b * NN + rowBase + r) * DOUTT + c4 * 4] = v;
    }
}

// ---------------------------------------------------------------------------
extern "C" void kernel_launch(void* const* d_in, const int* in_sizes, int n_in,
                              void* d_out, int out_size)
{
    const float* h   = (const float*)d_in[0];
    const int*   adj = (const int*)  d_in[1];
    const int*   pos = (const int*)  d_in[2];
    const float* W   = (const float*)d_in[3];
    const float* a1  = (const float*)d_in[4];
    const float* a2  = (const float*)d_in[5];
    const float* pt  = (const float*)d_in[6];

    float* out = (float*)d_out;
    float* hp  = out;                              // [B,N,DOUT]
    float* att = out + (long)BB * NN * DOUTT;      // [B,N,N]

    static int smem_set = 0;
    if (!smem_set) {
        cudaFuncSetAttribute(g1_gemm, cudaFuncAttributeMaxDynamicSharedMemorySize, G1_SMEM);
        cudaFuncSetAttribute(g2_fused, cudaFuncAttributeMaxDynamicSharedMemorySize, G2_SMEM);
        smem_set = 1;
    }

    dim3 gT(DINN / 32, DOUTT / 32);                // (24, 8)
    k_transW<<<gT, 256>>>(W);

    dim3 gG(NN / 64, BB);                          // (8, 32) = 256 CTAs
    g1_gemm<<<gG, 256, G1_SMEM>>>(h, pos, pt, a1, a2);

    g2_fused<<<gG, 256, G2_SMEM>>>(adj, att, hp);
}